// round 1
// baseline (speedup 1.0000x reference)
#include <cuda_runtime.h>
#include <math.h>

// ---------------- problem constants ----------------
#define NTOT  8192
#define BGR   128
#define NPER  64
#define EDIR  65536
#define EKEEP 32768
#define EU    256
#define FIN   5
#define H1D   256
#define H2D   512
#define ATT   1536
#define EPSV  1e-5f

// ---------------- scratch (device globals; no allocation allowed) ----------------
__device__ float g_w[EDIR];
__device__ float g_agg1[NTOT * FIN];
__device__ float g_h1[NTOT * H1D];
__device__ float g_agg2[NTOT * H1D];
__device__ float g_h2[NTOT * H2D];
__device__ int   g_esrc[EKEEP];
__device__ int   g_edst[EKEEP];
__device__ int   g_kidx[EKEEP];
__device__ float g_feat[(size_t)EKEEP * ATT];
__device__ float g_Wq[ATT * ATT];
__device__ float g_Wk[ATT * ATT];
__device__ float g_Wv[ATT * ATT];
__device__ float g_Wqk[ATT * ATT];
__device__ float g_Wvo[ATT * ATT];
__device__ float g_bq[ATT];
__device__ float g_bv[ATT];
__device__ float g_rvec[ATT];
__device__ float g_bvo[ATT];
__device__ float g_rv[EKEEP];
__device__ float g_G[(size_t)EKEEP * ATT];
__device__ float g_FVo[(size_t)EKEEP * ATT];
__device__ float g_S[(size_t)BGR * EU * EU];
__device__ float g_logits[EKEEP];

// ---------------- generic fp32 GEMM: 128x128x8 tiles, 8x8 per thread ----------------
// C[M,N] = alpha * A @ B (or A @ B^T) [+ C] [+ bias] [relu], batched via blockIdx.z.
// Requires: M%128==0, N%128==0, K%8==0, all leading dims %4==0. (All call sites satisfy.)
template<bool TB, bool ACC, bool RELU, bool HASB>
__global__ __launch_bounds__(256) void sgemm(
    const float* __restrict__ A, const float* __restrict__ B,
    float* __restrict__ C, const float* __restrict__ bias,
    int M, int N, int K, int lda, int ldb, int ldc,
    long long sA, long long sB, long long sC, long long sBias, float alpha)
{
    __shared__ float As[8][132];
    __shared__ float Bs[8][132];
    const int t  = threadIdx.x;
    const int bx = blockIdx.x, by = blockIdx.y, bz = blockIdx.z;
    const int n0 = bx * 128;
    const float* Ab = A + (long long)bz * sA + (long long)(by * 128) * lda;
    const float* Bb = B + (long long)bz * sB;
    float* Cb = C + (long long)bz * sC + (long long)(by * 128) * ldc + n0;

    float acc[8][8];
#pragma unroll
    for (int i = 0; i < 8; i++)
#pragma unroll
        for (int j = 0; j < 8; j++) acc[i][j] = 0.f;

    const int arow = t >> 1;
    const int ac4  = (t & 1) * 4;
    const int ty = t >> 4, tx = t & 15;

    for (int k0 = 0; k0 < K; k0 += 8) {
        float4 av = *reinterpret_cast<const float4*>(Ab + (long long)arow * lda + k0 + ac4);
        As[ac4 + 0][arow] = av.x; As[ac4 + 1][arow] = av.y;
        As[ac4 + 2][arow] = av.z; As[ac4 + 3][arow] = av.w;
        if (TB) {
            const int bc = t >> 1, bk = (t & 1) * 4;
            float4 bv = *reinterpret_cast<const float4*>(Bb + (long long)(n0 + bc) * ldb + k0 + bk);
            Bs[bk + 0][bc] = bv.x; Bs[bk + 1][bc] = bv.y;
            Bs[bk + 2][bc] = bv.z; Bs[bk + 3][bc] = bv.w;
        } else {
            const int br = t >> 5, bcol = (t & 31) * 4;
            float4 bv = *reinterpret_cast<const float4*>(Bb + (long long)(k0 + br) * ldb + n0 + bcol);
            *reinterpret_cast<float4*>(&Bs[br][bcol]) = bv;
        }
        __syncthreads();
#pragma unroll
        for (int kk = 0; kk < 8; kk++) {
            float a[8], b[8];
            *reinterpret_cast<float4*>(&a[0]) = *reinterpret_cast<const float4*>(&As[kk][ty * 8]);
            *reinterpret_cast<float4*>(&a[4]) = *reinterpret_cast<const float4*>(&As[kk][ty * 8 + 4]);
            *reinterpret_cast<float4*>(&b[0]) = *reinterpret_cast<const float4*>(&Bs[kk][tx * 8]);
            *reinterpret_cast<float4*>(&b[4]) = *reinterpret_cast<const float4*>(&Bs[kk][tx * 8 + 4]);
#pragma unroll
            for (int i = 0; i < 8; i++)
#pragma unroll
                for (int j = 0; j < 8; j++) acc[i][j] = fmaf(a[i], b[j], acc[i][j]);
        }
        __syncthreads();
    }

#pragma unroll
    for (int i = 0; i < 8; i++) {
        const int row = ty * 8 + i;
#pragma unroll
        for (int j = 0; j < 8; j += 4) {
            const int col = tx * 8 + j;
            float4 v;
            v.x = acc[i][j + 0] * alpha; v.y = acc[i][j + 1] * alpha;
            v.z = acc[i][j + 2] * alpha; v.w = acc[i][j + 3] * alpha;
            if (HASB) {
                const float* bp = bias + (long long)bz * sBias + n0 + col;
                v.x += bp[0]; v.y += bp[1]; v.z += bp[2]; v.w += bp[3];
            }
            if (ACC) {
                float4 c = *reinterpret_cast<const float4*>(&Cb[(long long)row * ldc + col]);
                v.x += c.x; v.y += c.y; v.z += c.z; v.w += c.w;
            }
            if (RELU) {
                v.x = fmaxf(v.x, 0.f); v.y = fmaxf(v.y, 0.f);
                v.z = fmaxf(v.z, 0.f); v.w = fmaxf(v.w, 0.f);
            }
            *reinterpret_cast<float4*>(&Cb[(long long)row * ldc + col]) = v;
        }
    }
}

// ---------------- small kernels ----------------
__global__ void k_edgew(const float* __restrict__ ea, const float* __restrict__ W,
                        const float* __restrict__ b) {
    int e = blockIdx.x * 256 + threadIdx.x;
    if (e < EDIR) {
        float a = ea[2 * e], c = ea[2 * e + 1];
        float v = a * W[0] + ((c < 0.5f) ? W[1] : W[2]) + b[0];
        g_w[e] = fmaxf(v, 0.f);
    }
}

__global__ void k_sc1(const int* __restrict__ edges, const float* __restrict__ x) {
    int e = blockIdx.x * 256 + threadIdx.x;
    if (e < EDIR) {
        int s = edges[e], d = edges[EDIR + e];
        float wv = g_w[e];
        if (wv != 0.f) {
#pragma unroll
            for (int f = 0; f < FIN; f++)
                atomicAdd(&g_agg1[d * FIN + f], wv * x[s * FIN + f]);
        }
    }
}

__global__ void k_gc1(const float* __restrict__ x, const float* __restrict__ Wrel,
                      const float* __restrict__ brel, const float* __restrict__ Wroot) {
    int idx = blockIdx.x * 256 + threadIdx.x;  // NTOT*H1D threads
    int n = idx >> 8, j = idx & 255;
    float s = brel[j];
#pragma unroll
    for (int f = 0; f < FIN; f++) {
        s += g_agg1[n * FIN + f] * Wrel[f * H1D + j];
        s += x[n * FIN + f] * Wroot[f * H1D + j];
    }
    g_h1[idx] = fmaxf(s, 0.f);
}

__global__ void k_sc2(const int* __restrict__ edges) {
    int e = blockIdx.x;              // EDIR blocks
    int t = threadIdx.x;             // 64 threads, 4 feats each
    int s = edges[e], d = edges[EDIR + e];
    float wv = g_w[e];
    if (wv == 0.f) return;
    float4 hv = *reinterpret_cast<const float4*>(&g_h1[s * H1D + t * 4]);
    atomicAdd(&g_agg2[d * H1D + t * 4 + 0], wv * hv.x);
    atomicAdd(&g_agg2[d * H1D + t * 4 + 1], wv * hv.y);
    atomicAdd(&g_agg2[d * H1D + t * 4 + 2], wv * hv.z);
    atomicAdd(&g_agg2[d * H1D + t * 4 + 3], wv * hv.w);
}

__global__ void k_gnorm(const float* __restrict__ gw, const float* __restrict__ gb,
                        const float* __restrict__ gms) {
    int g = blockIdx.x, j = threadIdx.x;  // 512 threads
    float s = 0.f;
    for (int n = 0; n < NPER; n++) s += g_h2[((g << 6) + n) * H2D + j];
    float mean = s * (1.f / NPER);
    float ms = gms[j];
    float off = ms * mean;
    float s2 = 0.f;
    for (int n = 0; n < NPER; n++) {
        float c = g_h2[((g << 6) + n) * H2D + j] - off;
        s2 += c * c;
    }
    float inv = rsqrtf(s2 * (1.f / NPER) + EPSV);
    float wv = gw[j], bv = gb[j];
    for (int n = 0; n < NPER; n++) {
        int idx = ((g << 6) + n) * H2D + j;
        g_h2[idx] = wv * (g_h2[idx] - off) * inv + bv;
    }
}

__global__ void k_sort(const int* __restrict__ edges) {
    __shared__ unsigned int key[256];
    int g = blockIdx.x, t = threadIdx.x;
    int ge = g * 512 + 256 + t;                 // kept edges = (hi,lo) half
    int s = edges[ge], d = edges[EDIR + ge];
    unsigned int k = ((unsigned)((s - (g << 6)) * 64 + (d - (g << 6))) << 8) | (unsigned)t;
    key[t] = k;
    __syncthreads();
    for (int kk = 2; kk <= 256; kk <<= 1) {
        for (int j = kk >> 1; j > 0; j >>= 1) {
            int ixj = t ^ j;
            if (ixj > t) {
                unsigned a = key[t], b = key[ixj];
                bool up = (t & kk) == 0;
                if ((a > b) == up) { key[t] = b; key[ixj] = a; }
            }
            __syncthreads();
        }
    }
    int slot = key[t] & 255;
    int ge2 = g * 512 + 256 + slot;
    int i = g * 256 + t;
    g_esrc[i] = edges[ge2];
    g_edst[i] = edges[EDIR + ge2];
    g_kidx[i] = ge2;
}

__global__ void k_feat(const float* __restrict__ ea, const float* __restrict__ eW,
                       const float* __restrict__ eb) {
    int i = blockIdx.x, t = threadIdx.x;  // 256 threads
    int s = g_esrc[i], d = g_edst[i], ke = g_kidx[i];
    float a = ea[2 * ke], c = ea[2 * ke + 1];
    float* F = g_feat + (long long)i * ATT;
    for (int j = t; j < H2D; j += 256) {
        F[j]        = g_h2[s * H2D + j];
        F[1024 + j] = g_h2[d * H2D + j];
        float e = a * eW[j] + ((c < 0.5f) ? eW[512 + j] : eW[1024 + j]) + eb[j];
        F[512 + j] = fmaxf(e, 0.f);
    }
}

// y[N] = x @ W + b   (W is [K,N] row-major with ldw)
__global__ void k_vecmat(const float* __restrict__ x, const float* __restrict__ W,
                         const float* __restrict__ b, float* __restrict__ y,
                         int K, int N, int ldw) {
    int j = blockIdx.x * 256 + threadIdx.x;
    if (j < N) {
        float s = b ? b[j] : 0.f;
        for (int i = 0; i < K; i++) s += x[i] * W[(long long)i * ldw + j];
        y[j] = s;
    }
}

// y[row] = scale * dot(W[row,:], x)   (W is [ATT,ATT])
__global__ void k_matvecr(const float* __restrict__ W, const float* __restrict__ x,
                          float* __restrict__ y, float scale) {
    int row = blockIdx.x, t = threadIdx.x;
    float s = 0.f;
    for (int j = t; j < ATT; j += 256) s += W[(long long)row * ATT + j] * x[j];
    __shared__ float red[256];
    red[t] = s; __syncthreads();
    for (int st = 128; st > 0; st >>= 1) { if (t < st) red[t] += red[t + st]; __syncthreads(); }
    if (t == 0) y[row] = red[0] * scale;
}

// rv[i] = dot(feat[i,:], g_rvec)
__global__ void k_rowdot() {
    int row = blockIdx.x, t = threadIdx.x;
    const float* F = g_feat + (long long)row * ATT;
    float s = 0.f;
    for (int j = t; j < ATT; j += 256) s += F[j] * g_rvec[j];
    __shared__ float red[256];
    red[t] = s; __syncthreads();
    for (int st = 128; st > 0; st >>= 1) { if (t < st) red[t] += red[t + st]; __syncthreads(); }
    if (t == 0) g_rv[row] = red[0];
}

__global__ void k_softmax() {
    int rb = blockIdx.x, t = threadIdx.x;  // EKEEP rows, 256 keys each
    float v = g_S[(long long)rb * 256 + t];
    __shared__ float red[256];
    red[t] = v; __syncthreads();
    for (int s = 128; s > 0; s >>= 1) { if (t < s) red[t] = fmaxf(red[t], red[t + s]); __syncthreads(); }
    float m = red[0]; __syncthreads();
    float e = __expf(v - m);
    red[t] = e; __syncthreads();
    for (int s = 128; s > 0; s >>= 1) { if (t < s) red[t] += red[t + s]; __syncthreads(); }
    g_S[(long long)rb * 256 + t] = e / red[0];
}

__global__ void k_ln_head(const float* __restrict__ lng, const float* __restrict__ lnb,
                          const float* __restrict__ hW, const float* __restrict__ hb) {
    int row = blockIdx.x, t = threadIdx.x;
    const float* x = g_feat + (long long)row * ATT;
    float loc[6];
    float s = 0.f;
#pragma unroll
    for (int i = 0; i < 6; i++) { loc[i] = x[t + i * 256]; s += loc[i]; }
    __shared__ float red[256];
    red[t] = s; __syncthreads();
    for (int st = 128; st > 0; st >>= 1) { if (t < st) red[t] += red[t + st]; __syncthreads(); }
    float mu = red[0] * (1.f / ATT); __syncthreads();
    float s2 = 0.f;
#pragma unroll
    for (int i = 0; i < 6; i++) { float d = loc[i] - mu; s2 += d * d; }
    red[t] = s2; __syncthreads();
    for (int st = 128; st > 0; st >>= 1) { if (t < st) red[t] += red[t + st]; __syncthreads(); }
    float inv = rsqrtf(red[0] * (1.f / ATT) + EPSV); __syncthreads();
    float o = 0.f;
#pragma unroll
    for (int i = 0; i < 6; i++) {
        int j = t + i * 256;
        float nv = lng[j] * (loc[i] - mu) * inv + lnb[j];
        o += nv * hW[j];
    }
    red[t] = o; __syncthreads();
    for (int st = 128; st > 0; st >>= 1) { if (t < st) red[t] += red[t + st]; __syncthreads(); }
    if (t == 0) g_logits[row] = red[0] + hb[0];
}

__global__ void k_final(const float* __restrict__ ea, float* __restrict__ out) {
    int idx = blockIdx.x * 256 + threadIdx.x;  // B*128 pairs
    if (idx < BGR * 128) {
        int i0 = 2 * idx, i1 = i0 + 1;   // pair (2p, 2p+1) within each graph block of 256
        float v0 = g_logits[i0], v1 = g_logits[i1];
        float c0 = ea[2 * g_kidx[i0] + 1], c1 = ea[2 * g_kidx[i1] + 1];
        int m = (v1 < v0) ? 1 : 0;       // argmin, first index wins ties
        out[idx * 2 + 0] = (float)g_esrc[i0];
        out[idx * 2 + 1] = (float)g_edst[i0];
        out[32768 + idx] = m ? v1 : v0;
        out[49152 + idx] = m ? c1 : c0;
    }
}

// ---------------- host-side GEMM dispatch ----------------
template<bool TB, bool ACC, bool RELU, bool HASB>
static void gemm(const float* A, const float* B, float* C, const float* bias,
                 int M, int N, int K, int lda, int ldb, int ldc,
                 long long sA, long long sB, long long sC, long long sBias,
                 float alpha, int batch) {
    dim3 grid(N / 128, M / 128, batch);
    sgemm<TB, ACC, RELU, HASB><<<grid, 256>>>(A, B, C, bias, M, N, K, lda, ldb, ldc,
                                              sA, sB, sC, sBias, alpha);
}

static float* sym(const void* s) {
    void* p = nullptr;
    cudaGetSymbolAddress(&p, s);
    return (float*)p;
}

extern "C" void kernel_launch(void* const* d_in, const int* in_sizes, int n_in,
                              void* d_out, int out_size) {
    const float* x       = (const float*)d_in[0];
    const int*   edges   = (const int*)d_in[1];
    const float* ea      = (const float*)d_in[2];
    const float* wembW   = (const float*)d_in[5];
    const float* wembB   = (const float*)d_in[6];
    const float* gc1Wrel = (const float*)d_in[7];
    const float* gc1brel = (const float*)d_in[8];
    const float* gc1Wroot= (const float*)d_in[9];
    const float* gc2Wrel = (const float*)d_in[10];
    const float* gc2brel = (const float*)d_in[11];
    const float* gc2Wroot= (const float*)d_in[12];
    const float* gnw     = (const float*)d_in[13];
    const float* gnb     = (const float*)d_in[14];
    const float* gnms    = (const float*)d_in[15];
    const float* eW      = (const float*)d_in[16];
    const float* ebias   = (const float*)d_in[17];
    const float* qkvW    = (const float*)d_in[18];
    const float* qkvb    = (const float*)d_in[19];
    const float* inWq    = (const float*)d_in[20];
    const float* inWk    = (const float*)d_in[21];
    const float* inWv    = (const float*)d_in[22];
    const float* inbq    = (const float*)d_in[23];
    const float* inbv    = (const float*)d_in[25];
    const float* outW    = (const float*)d_in[26];
    const float* outb    = (const float*)d_in[27];
    const float* lng     = (const float*)d_in[28];
    const float* lnb     = (const float*)d_in[29];
    const float* hW      = (const float*)d_in[30];
    const float* hb      = (const float*)d_in[31];
    (void)in_sizes; (void)n_in; (void)out_size;

    float* agg1 = sym(g_agg1);  float* agg2 = sym(g_agg2);
    float* h1   = sym(g_h1);    float* h2   = sym(g_h2);
    float* feat = sym(g_feat);
    float* Wq   = sym(g_Wq);    float* Wk   = sym(g_Wk);   float* Wv  = sym(g_Wv);
    float* Wqk  = sym(g_Wqk);   float* Wvo  = sym(g_Wvo);
    float* bq   = sym(g_bq);    float* bv   = sym(g_bv);
    float* rvec = sym(g_rvec);  float* bvo  = sym(g_bvo);  float* rv  = sym(g_rv);
    float* G    = sym(g_G);     float* FVo  = sym(g_FVo);  float* S   = sym(g_S);

    const float scale = 1.0f / sqrtf((float)ATT);

    cudaMemsetAsync(agg1, 0, sizeof(float) * NTOT * FIN, 0);
    cudaMemsetAsync(agg2, 0, sizeof(float) * NTOT * H1D, 0);

    // ---- GNN front-end ----
    k_edgew<<<EDIR / 256, 256>>>(ea, wembW, wembB);
    k_sc1<<<EDIR / 256, 256>>>(edges, x);
    k_gc1<<<NTOT * H1D / 256, 256>>>(x, gc1Wrel, gc1brel, gc1Wroot);
    k_sc2<<<EDIR, 64>>>(edges);
    gemm<false, false, false, false>(agg2, gc2Wrel, h2, nullptr,
                                     NTOT, H2D, H1D, H1D, H2D, H2D, 0, 0, 0, 0, 1.f, 1);
    gemm<false, true, true, true>(h1, gc2Wroot, h2, gc2brel,
                                  NTOT, H2D, H1D, H1D, H2D, H2D, 0, 0, 0, 0, 1.f, 1);
    k_gnorm<<<BGR, H2D>>>(gnw, gnb, gnms);

    // ---- edge selection + sort + feature assembly ----
    k_sort<<<BGR, 256>>>(edges);
    k_feat<<<EKEEP, 256>>>(ea, eW, ebias);

    // ---- weight folding ----
    gemm<false, false, false, false>(qkvW + 0,    inWq, Wq, nullptr, ATT, ATT, ATT, 3 * ATT, ATT, ATT, 0, 0, 0, 0, 1.f, 1);
    gemm<false, false, false, false>(qkvW + ATT,  inWk, Wk, nullptr, ATT, ATT, ATT, 3 * ATT, ATT, ATT, 0, 0, 0, 0, 1.f, 1);
    gemm<false, false, false, false>(qkvW + 2*ATT,inWv, Wv, nullptr, ATT, ATT, ATT, 3 * ATT, ATT, ATT, 0, 0, 0, 0, 1.f, 1);
    k_vecmat<<<ATT / 256, 256>>>(qkvb + 0,     inWq, inbq, bq, ATT, ATT, ATT);
    k_vecmat<<<ATT / 256, 256>>>(qkvb + 2*ATT, inWv, inbv, bv, ATT, ATT, ATT);
    k_matvecr<<<ATT, 256>>>(Wk, bq, rvec, scale);           // r = scale * Wk_eff @ bq_eff
    k_vecmat<<<ATT / 256, 256>>>(bv, outW, outb, bvo, ATT, ATT, ATT);
    gemm<true,  false, false, false>(Wq, Wk, Wqk, nullptr, ATT, ATT, ATT, ATT, ATT, ATT, 0, 0, 0, 0, scale, 1);
    gemm<false, false, false, false>(Wv, outW, Wvo, nullptr, ATT, ATT, ATT, ATT, ATT, ATT, 0, 0, 0, 0, 1.f, 1);

    // ---- attention ----
    k_rowdot<<<EKEEP, 256>>>();                             // rv = feat @ r
    gemm<false, false, false, false>(feat, Wqk, G, nullptr,
                                     EKEEP, ATT, ATT, ATT, ATT, ATT, 0, 0, 0, 0, 1.f, 1);
    gemm<false, false, false, true>(feat, Wvo, FVo, bvo,
                                    EKEEP, ATT, ATT, ATT, ATT, ATT, 0, 0, 0, 0, 1.f, 1);
    // scores[b] = G[b] @ feat[b]^T + rv[b]  (per-column bias)
    gemm<true, false, false, true>(G, feat, S, rv,
                                   EU, EU, ATT, ATT, ATT, EU,
                                   (long long)EU * ATT, (long long)EU * ATT,
                                   (long long)EU * EU, EU, 1.f, BGR);
    k_softmax<<<EKEEP, 256>>>();
    // feat += S[b] @ FVo[b]
    gemm<false, true, false, false>(S, FVo, feat, nullptr,
                                    EU, ATT, EU, EU, ATT, ATT,
                                    (long long)EU * EU, (long long)EU * ATT,
                                    (long long)EU * ATT, 0, 1.f, BGR);

    // ---- LN + head + pairing ----
    k_ln_head<<<EKEEP, 256>>>(lng, lnb, hW, hb);
    k_final<<<(BGR * 128) / 256, 256>>>(ea, (float*)d_out);
}

// round 3
// speedup vs baseline: 1.2170x; 1.2170x over previous
#include <cuda_runtime.h>
#include <math.h>
#include <stdint.h>

// ---------------- problem constants ----------------
#define NTOT  8192
#define BGR   128
#define NPER  64
#define EDIR  65536
#define EKEEP 32768
#define EU    256
#define FIN   5
#define H1D   256
#define H2D   512
#define ATT   1536
#define EPSV  1e-5f

// ---------------- scratch (device globals; no allocation allowed) ----------------
__device__ float g_w[EDIR];
__device__ float g_agg1[NTOT * FIN];
__device__ float g_h1[NTOT * H1D];
__device__ float g_agg2[NTOT * H1D];
__device__ float g_h2[NTOT * H2D];
__device__ int   g_esrc[EKEEP];
__device__ int   g_edst[EKEEP];
__device__ int   g_kidx[EKEEP];
__device__ float g_feat[(size_t)EKEEP * ATT];
__device__ float g_Wq[ATT * ATT];
__device__ float g_Wk[ATT * ATT];
__device__ float g_Wv[ATT * ATT];
__device__ float g_Wqk[ATT * ATT];
__device__ float g_Wvo[ATT * ATT];
__device__ float g_bq[ATT];
__device__ float g_bv[ATT];
__device__ float g_rvec[ATT];
__device__ float g_bvo[ATT];
__device__ float g_rv[EKEEP];
__device__ float g_G[(size_t)EKEEP * ATT];
__device__ float g_FVo[(size_t)EKEEP * ATT];
__device__ float g_S[(size_t)BGR * EU * EU];
__device__ float g_logits[EKEEP];

// ---------------- tf32 helpers ----------------
__device__ __forceinline__ uint32_t f2tf(float x) {
    uint32_t r;
    asm("cvt.rna.tf32.f32 %0, %1;" : "=r"(r) : "f"(x));
    return r;
}
// split x into (big, small) tf32 pair
__device__ __forceinline__ void tfsplit(float x, uint32_t& b, uint32_t& s) {
    b = f2tf(x);
    s = f2tf(x - __uint_as_float(b));
}

// ---------------- 3xTF32 tensor-core GEMM: 128x128x16 tiles ----------------
// C = alpha * A @ B (or A @ B^T) [+ C] [+ bias] [relu], batched via blockIdx.z.
// fp32-comparable precision via operand splitting: Ab*Bb + Ab*Bs + As*Bb.
// Requires: M%128==0, N%128==0, K%16==0, leading dims %4==0.
// 256 threads = 8 warps in 2(m) x 4(n); warp tile 64x32 via mma.m16n8k8.tf32.
template<bool TB, bool ACC, bool RELU, bool HASB>
__global__ __launch_bounds__(256) void tgemm(
    const float* __restrict__ A, const float* __restrict__ B,
    float* __restrict__ C, const float* __restrict__ bias,
    int M, int N, int K, int lda, int ldb, int ldc,
    long long sA, long long sB, long long sC, long long sBias, float alpha)
{
    __shared__ uint32_t AsB[128][20], AsS[128][20];   // [m][k] big/small
    __shared__ uint32_t BsB[16][136], BsS[16][136];   // [k][n] big/small

    const int t  = threadIdx.x;
    const int bx = blockIdx.x, by = blockIdx.y, bz = blockIdx.z;
    const int n0 = bx * 128;
    const float* Ab = A + (long long)bz * sA + (long long)(by * 128) * lda;
    const float* Bb = B + (long long)bz * sB;
    float* Cb = C + (long long)bz * sC + (long long)(by * 128) * ldc + n0;

    const int lane = t & 31, wid = t >> 5;
    const int grp = lane >> 2, qid = lane & 3;
    const int wm = (wid & 1) * 64;     // warp m-offset
    const int wn = (wid >> 1) * 32;    // warp n-offset

    float acc[4][4][4];
#pragma unroll
    for (int mi = 0; mi < 4; mi++)
#pragma unroll
        for (int nj = 0; nj < 4; nj++)
#pragma unroll
            for (int h = 0; h < 4; h++) acc[mi][nj][h] = 0.f;

    // global-load thread mapping (K-chunk = 16)
    const int ar = t >> 2, ac = (t & 3) * 4;    // A rows ar, ar+64; cols ac..ac+3
    const int br = t >> 5, bc = (t & 31) * 4;   // B rows br, br+8 (non-TB)
    const int tr = t >> 1, tk = (t & 1) * 8;    // TB: n-row tr, k cols tk..tk+7

    float4 ra[2], rb[2];

    auto gload = [&](int k0) {
        ra[0] = *reinterpret_cast<const float4*>(Ab + (long long)ar * lda + k0 + ac);
        ra[1] = *reinterpret_cast<const float4*>(Ab + (long long)(ar + 64) * lda + k0 + ac);
        if (TB) {
            rb[0] = *reinterpret_cast<const float4*>(Bb + (long long)(n0 + tr) * ldb + k0 + tk);
            rb[1] = *reinterpret_cast<const float4*>(Bb + (long long)(n0 + tr) * ldb + k0 + tk + 4);
        } else {
            rb[0] = *reinterpret_cast<const float4*>(Bb + (long long)(k0 + br) * ldb + n0 + bc);
            rb[1] = *reinterpret_cast<const float4*>(Bb + (long long)(k0 + br + 8) * ldb + n0 + bc);
        }
    };

    auto sstore = [&]() {
#pragma unroll
        for (int i = 0; i < 2; i++) {
            uint4 vb, vs;
            tfsplit(ra[i].x, vb.x, vs.x); tfsplit(ra[i].y, vb.y, vs.y);
            tfsplit(ra[i].z, vb.z, vs.z); tfsplit(ra[i].w, vb.w, vs.w);
            *reinterpret_cast<uint4*>(&AsB[i * 64 + ar][ac]) = vb;
            *reinterpret_cast<uint4*>(&AsS[i * 64 + ar][ac]) = vs;
        }
        if (TB) {
#pragma unroll
            for (int i = 0; i < 2; i++) {
                const float v[4] = {rb[i].x, rb[i].y, rb[i].z, rb[i].w};
#pragma unroll
                for (int j = 0; j < 4; j++) {
                    uint32_t b, s; tfsplit(v[j], b, s);
                    BsB[tk + i * 4 + j][tr] = b;
                    BsS[tk + i * 4 + j][tr] = s;
                }
            }
        } else {
#pragma unroll
            for (int i = 0; i < 2; i++) {
                uint4 vb, vs;
                tfsplit(rb[i].x, vb.x, vs.x); tfsplit(rb[i].y, vb.y, vs.y);
                tfsplit(rb[i].z, vb.z, vs.z); tfsplit(rb[i].w, vb.w, vs.w);
                *reinterpret_cast<uint4*>(&BsB[br + i * 8][bc]) = vb;
                *reinterpret_cast<uint4*>(&BsS[br + i * 8][bc]) = vs;
            }
        }
    };

    gload(0);
    sstore();
    __syncthreads();

    const int nk = K / 16;
    for (int kc = 0; kc < nk; kc++) {
        if (kc + 1 < nk) gload((kc + 1) * 16);

#pragma unroll
        for (int ks = 0; ks < 2; ks++) {
            const int k0 = ks * 8;
            uint32_t aB[4][4], aS[4][4];
#pragma unroll
            for (int mi = 0; mi < 4; mi++) {
                int r0 = wm + mi * 16 + grp;
                aB[mi][0] = AsB[r0][k0 + qid];
                aB[mi][1] = AsB[r0 + 8][k0 + qid];
                aB[mi][2] = AsB[r0][k0 + qid + 4];
                aB[mi][3] = AsB[r0 + 8][k0 + qid + 4];
                aS[mi][0] = AsS[r0][k0 + qid];
                aS[mi][1] = AsS[r0 + 8][k0 + qid];
                aS[mi][2] = AsS[r0][k0 + qid + 4];
                aS[mi][3] = AsS[r0 + 8][k0 + qid + 4];
            }
#pragma unroll
            for (int nj = 0; nj < 4; nj++) {
                int c0 = wn + nj * 8 + grp;
                uint32_t b0B = BsB[k0 + qid][c0];
                uint32_t b1B = BsB[k0 + qid + 4][c0];
                uint32_t b0S = BsS[k0 + qid][c0];
                uint32_t b1S = BsS[k0 + qid + 4][c0];
#pragma unroll
                for (int mi = 0; mi < 4; mi++) {
                    asm volatile(
                        "mma.sync.aligned.m16n8k8.row.col.f32.tf32.tf32.f32 "
                        "{%0,%1,%2,%3},{%4,%5,%6,%7},{%8,%9},{%0,%1,%2,%3};"
                        : "+f"(acc[mi][nj][0]), "+f"(acc[mi][nj][1]),
                          "+f"(acc[mi][nj][2]), "+f"(acc[mi][nj][3])
                        : "r"(aB[mi][0]), "r"(aB[mi][1]), "r"(aB[mi][2]), "r"(aB[mi][3]),
                          "r"(b0S), "r"(b1S));
                    asm volatile(
                        "mma.sync.aligned.m16n8k8.row.col.f32.tf32.tf32.f32 "
                        "{%0,%1,%2,%3},{%4,%5,%6,%7},{%8,%9},{%0,%1,%2,%3};"
                        : "+f"(acc[mi][nj][0]), "+f"(acc[mi][nj][1]),
                          "+f"(acc[mi][nj][2]), "+f"(acc[mi][nj][3])
                        : "r"(aS[mi][0]), "r"(aS[mi][1]), "r"(aS[mi][2]), "r"(aS[mi][3]),
                          "r"(b0B), "r"(b1B));
                    asm volatile(
                        "mma.sync.aligned.m16n8k8.row.col.f32.tf32.tf32.f32 "
                        "{%0,%1,%2,%3},{%4,%5,%6,%7},{%8,%9},{%0,%1,%2,%3};"
                        : "+f"(acc[mi][nj][0]), "+f"(acc[mi][nj][1]),
                          "+f"(acc[mi][nj][2]), "+f"(acc[mi][nj][3])
                        : "r"(aB[mi][0]), "r"(aB[mi][1]), "r"(aB[mi][2]), "r"(aB[mi][3]),
                          "r"(b0B), "r"(b1B));
                }
            }
        }

        __syncthreads();
        if (kc + 1 < nk) {
            sstore();
            __syncthreads();
        }
    }

    // epilogue
#pragma unroll
    for (int mi = 0; mi < 4; mi++) {
#pragma unroll
        for (int nj = 0; nj < 4; nj++) {
            int row = wm + mi * 16 + grp;
            int col = wn + nj * 8 + qid * 2;
#pragma unroll
            for (int h = 0; h < 2; h++) {
                int r = row + h * 8;
                float v0 = acc[mi][nj][h * 2 + 0] * alpha;
                float v1 = acc[mi][nj][h * 2 + 1] * alpha;
                if (HASB) {
                    const float* bp = bias + (long long)bz * sBias + n0 + col;
                    v0 += bp[0]; v1 += bp[1];
                }
                float2* cp = reinterpret_cast<float2*>(Cb + (long long)r * ldc + col);
                if (ACC) { float2 c = *cp; v0 += c.x; v1 += c.y; }
                if (RELU) { v0 = fmaxf(v0, 0.f); v1 = fmaxf(v1, 0.f); }
                *cp = make_float2(v0, v1);
            }
        }
    }
}

// ---------------- small kernels ----------------
__global__ void k_edgew(const float* __restrict__ ea, const float* __restrict__ W,
                        const float* __restrict__ b) {
    int e = blockIdx.x * 256 + threadIdx.x;
    if (e < EDIR) {
        float a = ea[2 * e], c = ea[2 * e + 1];
        float v = a * W[0] + ((c < 0.5f) ? W[1] : W[2]) + b[0];
        g_w[e] = fmaxf(v, 0.f);
    }
}

__global__ void k_sc1(const int* __restrict__ edges, const float* __restrict__ x) {
    int e = blockIdx.x * 256 + threadIdx.x;
    if (e < EDIR) {
        int s = edges[e], d = edges[EDIR + e];
        float wv = g_w[e];
        if (wv != 0.f) {
#pragma unroll
            for (int f = 0; f < FIN; f++)
                atomicAdd(&g_agg1[d * FIN + f], wv * x[s * FIN + f]);
        }
    }
}

__global__ void k_gc1(const float* __restrict__ x, const float* __restrict__ Wrel,
                      const float* __restrict__ brel, const float* __restrict__ Wroot) {
    int idx = blockIdx.x * 256 + threadIdx.x;  // NTOT*H1D threads
    int n = idx >> 8, j = idx & 255;
    float s = brel[j];
#pragma unroll
    for (int f = 0; f < FIN; f++) {
        s += g_agg1[n * FIN + f] * Wrel[f * H1D + j];
        s += x[n * FIN + f] * Wroot[f * H1D + j];
    }
    g_h1[idx] = fmaxf(s, 0.f);
}

__global__ void k_sc2(const int* __restrict__ edges) {
    int e = blockIdx.x;              // EDIR blocks
    int t = threadIdx.x;             // 64 threads, 4 feats each
    int s = edges[e], d = edges[EDIR + e];
    float wv = g_w[e];
    if (wv == 0.f) return;
    float4 hv = *reinterpret_cast<const float4*>(&g_h1[s * H1D + t * 4]);
    atomicAdd(&g_agg2[d * H1D + t * 4 + 0], wv * hv.x);
    atomicAdd(&g_agg2[d * H1D + t * 4 + 1], wv * hv.y);
    atomicAdd(&g_agg2[d * H1D + t * 4 + 2], wv * hv.z);
    atomicAdd(&g_agg2[d * H1D + t * 4 + 3], wv * hv.w);
}

__global__ void k_gnorm(const float* __restrict__ gw, const float* __restrict__ gb,
                        const float* __restrict__ gms) {
    int g = blockIdx.x, j = threadIdx.x;  // 512 threads
    float s = 0.f;
    for (int n = 0; n < NPER; n++) s += g_h2[((g << 6) + n) * H2D + j];
    float mean = s * (1.f / NPER);
    float ms = gms[j];
    float off = ms * mean;
    float s2 = 0.f;
    for (int n = 0; n < NPER; n++) {
        float c = g_h2[((g << 6) + n) * H2D + j] - off;
        s2 += c * c;
    }
    float inv = rsqrtf(s2 * (1.f / NPER) + EPSV);
    float wv = gw[j], bv = gb[j];
    for (int n = 0; n < NPER; n++) {
        int idx = ((g << 6) + n) * H2D + j;
        g_h2[idx] = wv * (g_h2[idx] - off) * inv + bv;
    }
}

__global__ void k_sort(const int* __restrict__ edges) {
    __shared__ unsigned int key[256];
    int g = blockIdx.x, t = threadIdx.x;
    int ge = g * 512 + 256 + t;                 // kept edges = (hi,lo) half
    int s = edges[ge], d = edges[EDIR + ge];
    unsigned int k = ((unsigned)((s - (g << 6)) * 64 + (d - (g << 6))) << 8) | (unsigned)t;
    key[t] = k;
    __syncthreads();
    for (int kk = 2; kk <= 256; kk <<= 1) {
        for (int j = kk >> 1; j > 0; j >>= 1) {
            int ixj = t ^ j;
            if (ixj > t) {
                unsigned a = key[t], b = key[ixj];
                bool up = (t & kk) == 0;
                if ((a > b) == up) { key[t] = b; key[ixj] = a; }
            }
            __syncthreads();
        }
    }
    int slot = key[t] & 255;
    int ge2 = g * 512 + 256 + slot;
    int i = g * 256 + t;
    g_esrc[i] = edges[ge2];
    g_edst[i] = edges[EDIR + ge2];
    g_kidx[i] = ge2;
}

__global__ void k_feat(const float* __restrict__ ea, const float* __restrict__ eW,
                       const float* __restrict__ eb) {
    int i = blockIdx.x, t = threadIdx.x;  // 256 threads
    int s = g_esrc[i], d = g_edst[i], ke = g_kidx[i];
    float a = ea[2 * ke], c = ea[2 * ke + 1];
    float* F = g_feat + (long long)i * ATT;
    for (int j = t; j < H2D; j += 256) {
        F[j]        = g_h2[s * H2D + j];
        F[1024 + j] = g_h2[d * H2D + j];
        float e = a * eW[j] + ((c < 0.5f) ? eW[512 + j] : eW[1024 + j]) + eb[j];
        F[512 + j] = fmaxf(e, 0.f);
    }
}

// y[N] = x @ W + b   (W is [K,N] row-major with ldw)
__global__ void k_vecmat(const float* __restrict__ x, const float* __restrict__ W,
                         const float* __restrict__ b, float* __restrict__ y,
                         int K, int N, int ldw) {
    int j = blockIdx.x * 256 + threadIdx.x;
    if (j < N) {
        float s = b ? b[j] : 0.f;
        for (int i = 0; i < K; i++) s += x[i] * W[(long long)i * ldw + j];
        y[j] = s;
    }
}

// y[row] = scale * dot(W[row,:], x)   (W is [ATT,ATT])
__global__ void k_matvecr(const float* __restrict__ W, const float* __restrict__ x,
                          float* __restrict__ y, float scale) {
    int row = blockIdx.x, t = threadIdx.x;
    float s = 0.f;
    for (int j = t; j < ATT; j += 256) s += W[(long long)row * ATT + j] * x[j];
    __shared__ float red[256];
    red[t] = s; __syncthreads();
    for (int st = 128; st > 0; st >>= 1) { if (t < st) red[t] += red[t + st]; __syncthreads(); }
    if (t == 0) y[row] = red[0] * scale;
}

// rv[i] = dot(feat[i,:], g_rvec)
__global__ void k_rowdot() {
    int row = blockIdx.x, t = threadIdx.x;
    const float* F = g_feat + (long long)row * ATT;
    float s = 0.f;
    for (int j = t; j < ATT; j += 256) s += F[j] * g_rvec[j];
    __shared__ float red[256];
    red[t] = s; __syncthreads();
    for (int st = 128; st > 0; st >>= 1) { if (t < st) red[t] += red[t + st]; __syncthreads(); }
    if (t == 0) g_rv[row] = red[0];
}

__global__ void k_softmax() {
    int rb = blockIdx.x, t = threadIdx.x;  // EKEEP rows, 256 keys each
    float v = g_S[(long long)rb * 256 + t];
    __shared__ float red[256];
    red[t] = v; __syncthreads();
    for (int s = 128; s > 0; s >>= 1) { if (t < s) red[t] = fmaxf(red[t], red[t + s]); __syncthreads(); }
    float m = red[0]; __syncthreads();
    float e = __expf(v - m);
    red[t] = e; __syncthreads();
    for (int s = 128; s > 0; s >>= 1) { if (t < s) red[t] += red[t + s]; __syncthreads(); }
    g_S[(long long)rb * 256 + t] = e / red[0];
}

__global__ void k_ln_head(const float* __restrict__ lng, const float* __restrict__ lnb,
                          const float* __restrict__ hW, const float* __restrict__ hb) {
    int row = blockIdx.x, t = threadIdx.x;
    const float* x = g_feat + (long long)row * ATT;
    float loc[6];
    float s = 0.f;
#pragma unroll
    for (int i = 0; i < 6; i++) { loc[i] = x[t + i * 256]; s += loc[i]; }
    __shared__ float red[256];
    red[t] = s; __syncthreads();
    for (int st = 128; st > 0; st >>= 1) { if (t < st) red[t] += red[t + st]; __syncthreads(); }
    float mu = red[0] * (1.f / ATT); __syncthreads();
    float s2 = 0.f;
#pragma unroll
    for (int i = 0; i < 6; i++) { float d = loc[i] - mu; s2 += d * d; }
    red[t] = s2; __syncthreads();
    for (int st = 128; st > 0; st >>= 1) { if (t < st) red[t] += red[t + st]; __syncthreads(); }
    float inv = rsqrtf(red[0] * (1.f / ATT) + EPSV); __syncthreads();
    float o = 0.f;
#pragma unroll
    for (int i = 0; i < 6; i++) {
        int j = t + i * 256;
        float nv = lng[j] * (loc[i] - mu) * inv + lnb[j];
        o += nv * hW[j];
    }
    red[t] = o; __syncthreads();
    for (int st = 128; st > 0; st >>= 1) { if (t < st) red[t] += red[t + st]; __syncthreads(); }
    if (t == 0) g_logits[row] = red[0] + hb[0];
}

__global__ void k_final(const float* __restrict__ ea, float* __restrict__ out) {
    int idx = blockIdx.x * 256 + threadIdx.x;  // B*128 pairs
    if (idx < BGR * 128) {
        int i0 = 2 * idx, i1 = i0 + 1;   // pair (2p, 2p+1) within each graph block of 256
        float v0 = g_logits[i0], v1 = g_logits[i1];
        float c0 = ea[2 * g_kidx[i0] + 1], c1 = ea[2 * g_kidx[i1] + 1];
        int m = (v1 < v0) ? 1 : 0;       // argmin, first index wins ties
        out[idx * 2 + 0] = (float)g_esrc[i0];
        out[idx * 2 + 1] = (float)g_edst[i0];
        out[32768 + idx] = m ? v1 : v0;
        out[49152 + idx] = m ? c1 : c0;
    }
}

// ---------------- host-side GEMM dispatch ----------------
template<bool TB, bool ACC, bool RELU, bool HASB>
static void gemm(const float* A, const float* B, float* C, const float* bias,
                 int M, int N, int K, int lda, int ldb, int ldc,
                 long long sA, long long sB, long long sC, long long sBias,
                 float alpha, int batch) {
    dim3 grid(N / 128, M / 128, batch);
    tgemm<TB, ACC, RELU, HASB><<<grid, 256>>>(A, B, C, bias, M, N, K, lda, ldb, ldc,
                                              sA, sB, sC, sBias, alpha);
}

static float* sym(const void* s) {
    void* p = nullptr;
    cudaGetSymbolAddress(&p, s);
    return (float*)p;
}

extern "C" void kernel_launch(void* const* d_in, const int* in_sizes, int n_in,
                              void* d_out, int out_size) {
    const float* x       = (const float*)d_in[0];
    const int*   edges   = (const int*)d_in[1];
    const float* ea      = (const float*)d_in[2];
    const float* wembW   = (const float*)d_in[5];
    const float* wembB   = (const float*)d_in[6];
    const float* gc1Wrel = (const float*)d_in[7];
    const float* gc1brel = (const float*)d_in[8];
    const float* gc1Wroot= (const float*)d_in[9];
    const float* gc2Wrel = (const float*)d_in[10];
    const float* gc2brel = (const float*)d_in[11];
    const float* gc2Wroot= (const float*)d_in[12];
    const float* gnw     = (const float*)d_in[13];
    const float* gnb     = (const float*)d_in[14];
    const float* gnms    = (const float*)d_in[15];
    const float* eW      = (const float*)d_in[16];
    const float* ebias   = (const float*)d_in[17];
    const float* qkvW    = (const float*)d_in[18];
    const float* qkvb    = (const float*)d_in[19];
    const float* inWq    = (const float*)d_in[20];
    const float* inWk    = (const float*)d_in[21];
    const float* inWv    = (const float*)d_in[22];
    const float* inbq    = (const float*)d_in[23];
    const float* inbv    = (const float*)d_in[25];
    const float* outW    = (const float*)d_in[26];
    const float* outb    = (const float*)d_in[27];
    const float* lng     = (const float*)d_in[28];
    const float* lnb     = (const float*)d_in[29];
    const float* hW      = (const float*)d_in[30];
    const float* hb      = (const float*)d_in[31];
    (void)in_sizes; (void)n_in; (void)out_size;

    float* agg1 = sym(g_agg1);  float* agg2 = sym(g_agg2);
    float* h1   = sym(g_h1);    float* h2   = sym(g_h2);
    float* feat = sym(g_feat);
    float* Wq   = sym(g_Wq);    float* Wk   = sym(g_Wk);   float* Wv  = sym(g_Wv);
    float* Wqk  = sym(g_Wqk);   float* Wvo  = sym(g_Wvo);
    float* bq   = sym(g_bq);    float* bv   = sym(g_bv);
    float* rvec = sym(g_rvec);  float* bvo  = sym(g_bvo);  float* rv  = sym(g_rv);
    float* G    = sym(g_G);     float* FVo  = sym(g_FVo);  float* S   = sym(g_S);

    const float scale = 1.0f / sqrtf((float)ATT);

    cudaMemsetAsync(agg1, 0, sizeof(float) * NTOT * FIN, 0);
    cudaMemsetAsync(agg2, 0, sizeof(float) * NTOT * H1D, 0);

    // ---- GNN front-end ----
    k_edgew<<<EDIR / 256, 256>>>(ea, wembW, wembB);
    k_sc1<<<EDIR / 256, 256>>>(edges, x);
    k_gc1<<<NTOT * H1D / 256, 256>>>(x, gc1Wrel, gc1brel, gc1Wroot);
    k_sc2<<<EDIR, 64>>>(edges);
    gemm<false, false, false, false>(agg2, gc2Wrel, h2, nullptr,
                                     NTOT, H2D, H1D, H1D, H2D, H2D, 0, 0, 0, 0, 1.f, 1);
    gemm<false, true, true, true>(h1, gc2Wroot, h2, gc2brel,
                                  NTOT, H2D, H1D, H1D, H2D, H2D, 0, 0, 0, 0, 1.f, 1);
    k_gnorm<<<BGR, H2D>>>(gnw, gnb, gnms);

    // ---- edge selection + sort + feature assembly ----
    k_sort<<<BGR, 256>>>(edges);
    k_feat<<<EKEEP, 256>>>(ea, eW, ebias);

    // ---- weight folding ----
    gemm<false, false, false, false>(qkvW + 0,    inWq, Wq, nullptr, ATT, ATT, ATT, 3 * ATT, ATT, ATT, 0, 0, 0, 0, 1.f, 1);
    gemm<false, false, false, false>(qkvW + ATT,  inWk, Wk, nullptr, ATT, ATT, ATT, 3 * ATT, ATT, ATT, 0, 0, 0, 0, 1.f, 1);
    gemm<false, false, false, false>(qkvW + 2*ATT,inWv, Wv, nullptr, ATT, ATT, ATT, 3 * ATT, ATT, ATT, 0, 0, 0, 0, 1.f, 1);
    k_vecmat<<<ATT / 256, 256>>>(qkvb + 0,     inWq, inbq, bq, ATT, ATT, ATT);
    k_vecmat<<<ATT / 256, 256>>>(qkvb + 2*ATT, inWv, inbv, bv, ATT, ATT, ATT);
    k_matvecr<<<ATT, 256>>>(Wk, bq, rvec, scale);           // r = scale * Wk_eff @ bq_eff
    k_vecmat<<<ATT / 256, 256>>>(bv, outW, outb, bvo, ATT, ATT, ATT);
    gemm<true,  false, false, false>(Wq, Wk, Wqk, nullptr, ATT, ATT, ATT, ATT, ATT, ATT, 0, 0, 0, 0, scale, 1);
    gemm<false, false, false, false>(Wv, outW, Wvo, nullptr, ATT, ATT, ATT, ATT, ATT, ATT, 0, 0, 0, 0, 1.f, 1);

    // ---- attention ----
    k_rowdot<<<EKEEP, 256>>>();                             // rv = feat @ r
    gemm<false, false, false, false>(feat, Wqk, G, nullptr,
                                     EKEEP, ATT, ATT, ATT, ATT, ATT, 0, 0, 0, 0, 1.f, 1);
    gemm<false, false, false, true>(feat, Wvo, FVo, bvo,
                                    EKEEP, ATT, ATT, ATT, ATT, ATT, 0, 0, 0, 0, 1.f, 1);
    // scores[b] = G[b] @ feat[b]^T + rv[b]  (per-column bias)
    gemm<true, false, false, true>(G, feat, S, rv,
                                   EU, EU, ATT, ATT, ATT, EU,
                                   (long long)EU * ATT, (long long)EU * ATT,
                                   (long long)EU * EU, EU, 1.f, BGR);
    k_softmax<<<EKEEP, 256>>>();
    // feat += S[b] @ FVo[b]
    gemm<false, true, false, false>(S, FVo, feat, nullptr,
                                    EU, ATT, EU, EU, ATT, ATT,
                                    (long long)EU * EU, (long long)EU * ATT,
                                    (long long)EU * ATT, 0, 1.f, BGR);

    // ---- LN + head + pairing ----
    k_ln_head<<<EKEEP, 256>>>(lng, lnb, hW, hb);
    k_final<<<(BGR * 128) / 256, 256>>>(ea, (float*)d_out);
}

// round 4
// speedup vs baseline: 1.6960x; 1.3936x over previous
#include <cuda_runtime.h>
#include <math.h>
#include <stdint.h>

// ---------------- problem constants ----------------
#define NTOT  8192
#define BGR   128
#define NPER  64
#define EDIR  65536
#define EKEEP 32768
#define EU    256
#define FIN   5
#define H1D   256
#define H2D   512
#define ATT   1536
#define EPSV  1e-5f

// ---------------- scratch (device globals; no allocation allowed) ----------------
__device__ float g_w[EDIR];
__device__ float g_agg1[NTOT * FIN];
__device__ float g_h1[NTOT * H1D];
__device__ float g_agg2[NTOT * H1D];
__device__ float g_h2[NTOT * H2D];
__device__ int   g_esrc[EKEEP];
__device__ int   g_edst[EKEEP];
__device__ int   g_kidx[EKEEP];
__device__ float g_feat[(size_t)EKEEP * ATT];
__device__ float g_Wq[ATT * ATT];
__device__ float g_Wk[ATT * ATT];
__device__ float g_Wv[ATT * ATT];
__device__ float g_Wqk[ATT * ATT];
__device__ float g_Wvo[ATT * ATT];
__device__ float g_bq[ATT];
__device__ float g_bv[ATT];
__device__ float g_rvec[ATT];
__device__ float g_bvo[ATT];
__device__ float g_rv[EKEEP];
__device__ float g_G[(size_t)EKEEP * ATT];
__device__ float g_FVo[(size_t)EKEEP * ATT];
__device__ float g_P1[(size_t)NTOT * ATT];   // h2 @ Wqk_top
__device__ float g_P3[(size_t)NTOT * ATT];   // h2 @ Wqk_bot
__device__ float g_Q1[(size_t)NTOT * ATT];   // h2 @ Wvo_top
__device__ float g_Q3[(size_t)NTOT * ATT];   // h2 @ Wvo_bot
__device__ float g_S[(size_t)BGR * EU * EU];
__device__ float g_logits[EKEEP];

// ---------------- tf32 helpers ----------------
__device__ __forceinline__ uint32_t f2tf(float x) {
    uint32_t r;
    asm("cvt.rna.tf32.f32 %0, %1;" : "=r"(r) : "f"(x));
    return r;
}
__device__ __forceinline__ void tfsplit(float x, uint32_t& b, uint32_t& s) {
    b = f2tf(x);
    s = f2tf(x - __uint_as_float(b));
}

// ---------------- 3xTF32 tensor-core GEMM: 128x128x16 tiles ----------------
// C = alpha * A @ B (or A @ B^T) [+ C] [+ bias] [relu], batched via blockIdx.z.
// fp32-comparable precision: Ab*Bb + Ab*Bs + As*Bb.
// Requires: M%128==0, N%128==0, K%16==0, leading dims %4==0.
template<bool TB, bool ACC, bool RELU, bool HASB>
__global__ __launch_bounds__(256) void tgemm(
    const float* __restrict__ A, const float* __restrict__ B,
    float* __restrict__ C, const float* __restrict__ bias,
    int M, int N, int K, int lda, int ldb, int ldc,
    long long sA, long long sB, long long sC, long long sBias, float alpha)
{
    __shared__ uint32_t AsB[128][20], AsS[128][20];   // [m][k] big/small
    __shared__ uint32_t BsB[16][136], BsS[16][136];   // [k][n] big/small

    const int t  = threadIdx.x;
    const int bx = blockIdx.x, by = blockIdx.y, bz = blockIdx.z;
    const int n0 = bx * 128;
    const float* Ab = A + (long long)bz * sA + (long long)(by * 128) * lda;
    const float* Bb = B + (long long)bz * sB;
    float* Cb = C + (long long)bz * sC + (long long)(by * 128) * ldc + n0;

    const int lane = t & 31, wid = t >> 5;
    const int grp = lane >> 2, qid = lane & 3;
    const int wm = (wid & 1) * 64;
    const int wn = (wid >> 1) * 32;

    float acc[4][4][4];
#pragma unroll
    for (int mi = 0; mi < 4; mi++)
#pragma unroll
        for (int nj = 0; nj < 4; nj++)
#pragma unroll
            for (int h = 0; h < 4; h++) acc[mi][nj][h] = 0.f;

    const int ar = t >> 2, ac = (t & 3) * 4;
    const int br = t >> 5, bc = (t & 31) * 4;
    const int tr = t >> 1, tk = (t & 1) * 8;

    float4 ra[2], rb[2];

    auto gload = [&](int k0) {
        ra[0] = *reinterpret_cast<const float4*>(Ab + (long long)ar * lda + k0 + ac);
        ra[1] = *reinterpret_cast<const float4*>(Ab + (long long)(ar + 64) * lda + k0 + ac);
        if (TB) {
            rb[0] = *reinterpret_cast<const float4*>(Bb + (long long)(n0 + tr) * ldb + k0 + tk);
            rb[1] = *reinterpret_cast<const float4*>(Bb + (long long)(n0 + tr) * ldb + k0 + tk + 4);
        } else {
            rb[0] = *reinterpret_cast<const float4*>(Bb + (long long)(k0 + br) * ldb + n0 + bc);
            rb[1] = *reinterpret_cast<const float4*>(Bb + (long long)(k0 + br + 8) * ldb + n0 + bc);
        }
    };

    auto sstore = [&]() {
#pragma unroll
        for (int i = 0; i < 2; i++) {
            uint4 vb, vs;
            tfsplit(ra[i].x, vb.x, vs.x); tfsplit(ra[i].y, vb.y, vs.y);
            tfsplit(ra[i].z, vb.z, vs.z); tfsplit(ra[i].w, vb.w, vs.w);
            *reinterpret_cast<uint4*>(&AsB[i * 64 + ar][ac]) = vb;
            *reinterpret_cast<uint4*>(&AsS[i * 64 + ar][ac]) = vs;
        }
        if (TB) {
#pragma unroll
            for (int i = 0; i < 2; i++) {
                const float v[4] = {rb[i].x, rb[i].y, rb[i].z, rb[i].w};
#pragma unroll
                for (int j = 0; j < 4; j++) {
                    uint32_t b, s; tfsplit(v[j], b, s);
                    BsB[tk + i * 4 + j][tr] = b;
                    BsS[tk + i * 4 + j][tr] = s;
                }
            }
        } else {
#pragma unroll
            for (int i = 0; i < 2; i++) {
                uint4 vb, vs;
                tfsplit(rb[i].x, vb.x, vs.x); tfsplit(rb[i].y, vb.y, vs.y);
                tfsplit(rb[i].z, vb.z, vs.z); tfsplit(rb[i].w, vb.w, vs.w);
                *reinterpret_cast<uint4*>(&BsB[br + i * 8][bc]) = vb;
                *reinterpret_cast<uint4*>(&BsS[br + i * 8][bc]) = vs;
            }
        }
    };

    gload(0);
    sstore();
    __syncthreads();

    const int nk = K / 16;
    for (int kc = 0; kc < nk; kc++) {
        if (kc + 1 < nk) gload((kc + 1) * 16);

#pragma unroll
        for (int ks = 0; ks < 2; ks++) {
            const int k0 = ks * 8;
            uint32_t aB[4][4], aS[4][4];
#pragma unroll
            for (int mi = 0; mi < 4; mi++) {
                int r0 = wm + mi * 16 + grp;
                aB[mi][0] = AsB[r0][k0 + qid];
                aB[mi][1] = AsB[r0 + 8][k0 + qid];
                aB[mi][2] = AsB[r0][k0 + qid + 4];
                aB[mi][3] = AsB[r0 + 8][k0 + qid + 4];
                aS[mi][0] = AsS[r0][k0 + qid];
                aS[mi][1] = AsS[r0 + 8][k0 + qid];
                aS[mi][2] = AsS[r0][k0 + qid + 4];
                aS[mi][3] = AsS[r0 + 8][k0 + qid + 4];
            }
#pragma unroll
            for (int nj = 0; nj < 4; nj++) {
                int c0 = wn + nj * 8 + grp;
                uint32_t b0B = BsB[k0 + qid][c0];
                uint32_t b1B = BsB[k0 + qid + 4][c0];
                uint32_t b0S = BsS[k0 + qid][c0];
                uint32_t b1S = BsS[k0 + qid + 4][c0];
#pragma unroll
                for (int mi = 0; mi < 4; mi++) {
                    asm volatile(
                        "mma.sync.aligned.m16n8k8.row.col.f32.tf32.tf32.f32 "
                        "{%0,%1,%2,%3},{%4,%5,%6,%7},{%8,%9},{%0,%1,%2,%3};"
                        : "+f"(acc[mi][nj][0]), "+f"(acc[mi][nj][1]),
                          "+f"(acc[mi][nj][2]), "+f"(acc[mi][nj][3])
                        : "r"(aB[mi][0]), "r"(aB[mi][1]), "r"(aB[mi][2]), "r"(aB[mi][3]),
                          "r"(b0S), "r"(b1S));
                    asm volatile(
                        "mma.sync.aligned.m16n8k8.row.col.f32.tf32.tf32.f32 "
                        "{%0,%1,%2,%3},{%4,%5,%6,%7},{%8,%9},{%0,%1,%2,%3};"
                        : "+f"(acc[mi][nj][0]), "+f"(acc[mi][nj][1]),
                          "+f"(acc[mi][nj][2]), "+f"(acc[mi][nj][3])
                        : "r"(aS[mi][0]), "r"(aS[mi][1]), "r"(aS[mi][2]), "r"(aS[mi][3]),
                          "r"(b0B), "r"(b1B));
                    asm volatile(
                        "mma.sync.aligned.m16n8k8.row.col.f32.tf32.tf32.f32 "
                        "{%0,%1,%2,%3},{%4,%5,%6,%7},{%8,%9},{%0,%1,%2,%3};"
                        : "+f"(acc[mi][nj][0]), "+f"(acc[mi][nj][1]),
                          "+f"(acc[mi][nj][2]), "+f"(acc[mi][nj][3])
                        : "r"(aB[mi][0]), "r"(aB[mi][1]), "r"(aB[mi][2]), "r"(aB[mi][3]),
                          "r"(b0B), "r"(b1B));
                }
            }
        }

        __syncthreads();
        if (kc + 1 < nk) {
            sstore();
            __syncthreads();
        }
    }

#pragma unroll
    for (int mi = 0; mi < 4; mi++) {
#pragma unroll
        for (int nj = 0; nj < 4; nj++) {
            int row = wm + mi * 16 + grp;
            int col = wn + nj * 8 + qid * 2;
#pragma unroll
            for (int h = 0; h < 2; h++) {
                int r = row + h * 8;
                float v0 = acc[mi][nj][h * 2 + 0] * alpha;
                float v1 = acc[mi][nj][h * 2 + 1] * alpha;
                if (HASB) {
                    const float* bp = bias + (long long)bz * sBias + n0 + col;
                    v0 += bp[0]; v1 += bp[1];
                }
                float2* cp = reinterpret_cast<float2*>(Cb + (long long)r * ldc + col);
                if (ACC) { float2 c = *cp; v0 += c.x; v1 += c.y; }
                if (RELU) { v0 = fmaxf(v0, 0.f); v1 = fmaxf(v1, 0.f); }
                *cp = make_float2(v0, v1);
            }
        }
    }
}

// ---------------- small kernels ----------------
__global__ void k_edgew(const float* __restrict__ ea, const float* __restrict__ W,
                        const float* __restrict__ b) {
    int e = blockIdx.x * 256 + threadIdx.x;
    if (e < EDIR) {
        float a = ea[2 * e], c = ea[2 * e + 1];
        float v = a * W[0] + ((c < 0.5f) ? W[1] : W[2]) + b[0];
        g_w[e] = fmaxf(v, 0.f);
    }
}

__global__ void k_sc1(const int* __restrict__ edges, const float* __restrict__ x) {
    int e = blockIdx.x * 256 + threadIdx.x;
    if (e < EDIR) {
        int s = edges[e], d = edges[EDIR + e];
        float wv = g_w[e];
        if (wv != 0.f) {
#pragma unroll
            for (int f = 0; f < FIN; f++)
                atomicAdd(&g_agg1[d * FIN + f], wv * x[s * FIN + f]);
        }
    }
}

__global__ void k_gc1(const float* __restrict__ x, const float* __restrict__ Wrel,
                      const float* __restrict__ brel, const float* __restrict__ Wroot) {
    int idx = blockIdx.x * 256 + threadIdx.x;
    int n = idx >> 8, j = idx & 255;
    float s = brel[j];
#pragma unroll
    for (int f = 0; f < FIN; f++) {
        s += g_agg1[n * FIN + f] * Wrel[f * H1D + j];
        s += x[n * FIN + f] * Wroot[f * H1D + j];
    }
    g_h1[idx] = fmaxf(s, 0.f);
}

__global__ void k_sc2(const int* __restrict__ edges) {
    int e = blockIdx.x;
    int t = threadIdx.x;
    int s = edges[e], d = edges[EDIR + e];
    float wv = g_w[e];
    if (wv == 0.f) return;
    float4 hv = *reinterpret_cast<const float4*>(&g_h1[s * H1D + t * 4]);
    atomicAdd(&g_agg2[d * H1D + t * 4 + 0], wv * hv.x);
    atomicAdd(&g_agg2[d * H1D + t * 4 + 1], wv * hv.y);
    atomicAdd(&g_agg2[d * H1D + t * 4 + 2], wv * hv.z);
    atomicAdd(&g_agg2[d * H1D + t * 4 + 3], wv * hv.w);
}

__global__ void k_gnorm(const float* __restrict__ gw, const float* __restrict__ gb,
                        const float* __restrict__ gms) {
    int g = blockIdx.x, j = threadIdx.x;
    float s = 0.f;
    for (int n = 0; n < NPER; n++) s += g_h2[((g << 6) + n) * H2D + j];
    float mean = s * (1.f / NPER);
    float ms = gms[j];
    float off = ms * mean;
    float s2 = 0.f;
    for (int n = 0; n < NPER; n++) {
        float c = g_h2[((g << 6) + n) * H2D + j] - off;
        s2 += c * c;
    }
    float inv = rsqrtf(s2 * (1.f / NPER) + EPSV);
    float wv = gw[j], bv = gb[j];
    for (int n = 0; n < NPER; n++) {
        int idx = ((g << 6) + n) * H2D + j;
        g_h2[idx] = wv * (g_h2[idx] - off) * inv + bv;
    }
}

__global__ void k_sort(const int* __restrict__ edges) {
    __shared__ unsigned int key[256];
    int g = blockIdx.x, t = threadIdx.x;
    int ge = g * 512 + 256 + t;
    int s = edges[ge], d = edges[EDIR + ge];
    unsigned int k = ((unsigned)((s - (g << 6)) * 64 + (d - (g << 6))) << 8) | (unsigned)t;
    key[t] = k;
    __syncthreads();
    for (int kk = 2; kk <= 256; kk <<= 1) {
        for (int j = kk >> 1; j > 0; j >>= 1) {
            int ixj = t ^ j;
            if (ixj > t) {
                unsigned a = key[t], b = key[ixj];
                bool up = (t & kk) == 0;
                if ((a > b) == up) { key[t] = b; key[ixj] = a; }
            }
            __syncthreads();
        }
    }
    int slot = key[t] & 255;
    int ge2 = g * 512 + 256 + slot;
    int i = g * 256 + t;
    g_esrc[i] = edges[ge2];
    g_edst[i] = edges[EDIR + ge2];
    g_kidx[i] = ge2;
}

__global__ void k_feat(const float* __restrict__ ea, const float* __restrict__ eW,
                       const float* __restrict__ eb) {
    int i = blockIdx.x, t = threadIdx.x;
    int s = g_esrc[i], d = g_edst[i], ke = g_kidx[i];
    float a = ea[2 * ke], c = ea[2 * ke + 1];
    float* F = g_feat + (long long)i * ATT;
    for (int j = t; j < H2D; j += 256) {
        F[j]        = g_h2[s * H2D + j];
        F[1024 + j] = g_h2[d * H2D + j];
        float e = a * eW[j] + ((c < 0.5f) ? eW[512 + j] : eW[1024 + j]) + eb[j];
        F[512 + j] = fmaxf(e, 0.f);
    }
}

// G[i] += P1[src_i] + P3[dst_i];  FVo[i] += Q1[src_i] + Q3[dst_i]
__global__ void k_gadd() {
    int i = blockIdx.x, t = threadIdx.x;
    int s = g_esrc[i], d = g_edst[i];
    const float4* p1 = reinterpret_cast<const float4*>(g_P1 + (long long)s * ATT);
    const float4* p3 = reinterpret_cast<const float4*>(g_P3 + (long long)d * ATT);
    const float4* q1 = reinterpret_cast<const float4*>(g_Q1 + (long long)s * ATT);
    const float4* q3 = reinterpret_cast<const float4*>(g_Q3 + (long long)d * ATT);
    float4* gr = reinterpret_cast<float4*>(g_G + (long long)i * ATT);
    float4* fr = reinterpret_cast<float4*>(g_FVo + (long long)i * ATT);
#pragma unroll
    for (int jj = 0; jj < 2; jj++) {
        int j = t + jj * 256;
        if (j < ATT / 4) {
            float4 g = gr[j], a = p1[j], b = p3[j];
            g.x += a.x + b.x; g.y += a.y + b.y; g.z += a.z + b.z; g.w += a.w + b.w;
            gr[j] = g;
            float4 f = fr[j], c = q1[j], e = q3[j];
            f.x += c.x + e.x; f.y += c.y + e.y; f.z += c.z + e.z; f.w += c.w + e.w;
            fr[j] = f;
        }
    }
}

// y[N] = x @ W + b   (W is [K,N] row-major with ldw)
__global__ void k_vecmat(const float* __restrict__ x, const float* __restrict__ W,
                         const float* __restrict__ b, float* __restrict__ y,
                         int K, int N, int ldw) {
    int j = blockIdx.x * 256 + threadIdx.x;
    if (j < N) {
        float s = b ? b[j] : 0.f;
        for (int i = 0; i < K; i++) s += x[i] * W[(long long)i * ldw + j];
        y[j] = s;
    }
}

// y[row] = scale * dot(W[row,:], x)
__global__ void k_matvecr(const float* __restrict__ W, const float* __restrict__ x,
                          float* __restrict__ y, float scale) {
    int row = blockIdx.x, t = threadIdx.x;
    float s = 0.f;
    for (int j = t; j < ATT; j += 256) s += W[(long long)row * ATT + j] * x[j];
    __shared__ float red[256];
    red[t] = s; __syncthreads();
    for (int st = 128; st > 0; st >>= 1) { if (t < st) red[t] += red[t + st]; __syncthreads(); }
    if (t == 0) y[row] = red[0] * scale;
}

// rv[i] = dot(feat[i,:], g_rvec)
__global__ void k_rowdot() {
    int row = blockIdx.x, t = threadIdx.x;
    const float* F = g_feat + (long long)row * ATT;
    float s = 0.f;
    for (int j = t; j < ATT; j += 256) s += F[j] * g_rvec[j];
    __shared__ float red[256];
    red[t] = s; __syncthreads();
    for (int st = 128; st > 0; st >>= 1) { if (t < st) red[t] += red[t + st]; __syncthreads(); }
    if (t == 0) g_rv[row] = red[0];
}

__global__ void k_softmax() {
    int rb = blockIdx.x, t = threadIdx.x;
    float v = g_S[(long long)rb * 256 + t];
    __shared__ float red[256];
    red[t] = v; __syncthreads();
    for (int s = 128; s > 0; s >>= 1) { if (t < s) red[t] = fmaxf(red[t], red[t + s]); __syncthreads(); }
    float m = red[0]; __syncthreads();
    float e = __expf(v - m);
    red[t] = e; __syncthreads();
    for (int s = 128; s > 0; s >>= 1) { if (t < s) red[t] += red[t + s]; __syncthreads(); }
    g_S[(long long)rb * 256 + t] = e / red[0];
}

__global__ void k_ln_head(const float* __restrict__ lng, const float* __restrict__ lnb,
                          const float* __restrict__ hW, const float* __restrict__ hb) {
    int row = blockIdx.x, t = threadIdx.x;
    const float* x = g_feat + (long long)row * ATT;
    float loc[6];
    float s = 0.f;
#pragma unroll
    for (int i = 0; i < 6; i++) { loc[i] = x[t + i * 256]; s += loc[i]; }
    __shared__ float red[256];
    red[t] = s; __syncthreads();
    for (int st = 128; st > 0; st >>= 1) { if (t < st) red[t] += red[t + st]; __syncthreads(); }
    float mu = red[0] * (1.f / ATT); __syncthreads();
    float s2 = 0.f;
#pragma unroll
    for (int i = 0; i < 6; i++) { float d = loc[i] - mu; s2 += d * d; }
    red[t] = s2; __syncthreads();
    for (int st = 128; st > 0; st >>= 1) { if (t < st) red[t] += red[t + st]; __syncthreads(); }
    float inv = rsqrtf(red[0] * (1.f / ATT) + EPSV); __syncthreads();
    float o = 0.f;
#pragma unroll
    for (int i = 0; i < 6; i++) {
        int j = t + i * 256;
        float nv = lng[j] * (loc[i] - mu) * inv + lnb[j];
        o += nv * hW[j];
    }
    red[t] = o; __syncthreads();
    for (int st = 128; st > 0; st >>= 1) { if (t < st) red[t] += red[t + st]; __syncthreads(); }
    if (t == 0) g_logits[row] = red[0] + hb[0];
}

__global__ void k_final(const float* __restrict__ ea, float* __restrict__ out) {
    int idx = blockIdx.x * 256 + threadIdx.x;
    if (idx < BGR * 128) {
        int i0 = 2 * idx, i1 = i0 + 1;
        float v0 = g_logits[i0], v1 = g_logits[i1];
        float c0 = ea[2 * g_kidx[i0] + 1], c1 = ea[2 * g_kidx[i1] + 1];
        int m = (v1 < v0) ? 1 : 0;
        out[idx * 2 + 0] = (float)g_esrc[i0];
        out[idx * 2 + 1] = (float)g_edst[i0];
        out[32768 + idx] = m ? v1 : v0;
        out[49152 + idx] = m ? c1 : c0;
    }
}

// ---------------- host-side GEMM dispatch ----------------
template<bool TB, bool ACC, bool RELU, bool HASB>
static void gemm(const float* A, const float* B, float* C, const float* bias,
                 int M, int N, int K, int lda, int ldb, int ldc,
                 long long sA, long long sB, long long sC, long long sBias,
                 float alpha, int batch) {
    dim3 grid(N / 128, M / 128, batch);
    tgemm<TB, ACC, RELU, HASB><<<grid, 256>>>(A, B, C, bias, M, N, K, lda, ldb, ldc,
                                              sA, sB, sC, sBias, alpha);
}

static float* sym(const void* s) {
    void* p = nullptr;
    cudaGetSymbolAddress(&p, s);
    return (float*)p;
}

extern "C" void kernel_launch(void* const* d_in, const int* in_sizes, int n_in,
                              void* d_out, int out_size) {
    const float* x       = (const float*)d_in[0];
    const int*   edges   = (const int*)d_in[1];
    const float* ea      = (const float*)d_in[2];
    const float* wembW   = (const float*)d_in[5];
    const float* wembB   = (const float*)d_in[6];
    const float* gc1Wrel = (const float*)d_in[7];
    const float* gc1brel = (const float*)d_in[8];
    const float* gc1Wroot= (const float*)d_in[9];
    const float* gc2Wrel = (const float*)d_in[10];
    const float* gc2brel = (const float*)d_in[11];
    const float* gc2Wroot= (const float*)d_in[12];
    const float* gnw     = (const float*)d_in[13];
    const float* gnb     = (const float*)d_in[14];
    const float* gnms    = (const float*)d_in[15];
    const float* eW      = (const float*)d_in[16];
    const float* ebias   = (const float*)d_in[17];
    const float* qkvW    = (const float*)d_in[18];
    const float* qkvb    = (const float*)d_in[19];
    const float* inWq    = (const float*)d_in[20];
    const float* inWk    = (const float*)d_in[21];
    const float* inWv    = (const float*)d_in[22];
    const float* inbq    = (const float*)d_in[23];
    const float* inbv    = (const float*)d_in[25];
    const float* outW    = (const float*)d_in[26];
    const float* outb    = (const float*)d_in[27];
    const float* lng     = (const float*)d_in[28];
    const float* lnb     = (const float*)d_in[29];
    const float* hW      = (const float*)d_in[30];
    const float* hb      = (const float*)d_in[31];
    (void)in_sizes; (void)n_in; (void)out_size;

    float* agg1 = sym(g_agg1);  float* agg2 = sym(g_agg2);
    float* h1   = sym(g_h1);    float* h2   = sym(g_h2);
    float* feat = sym(g_feat);
    float* Wq   = sym(g_Wq);    float* Wk   = sym(g_Wk);   float* Wv  = sym(g_Wv);
    float* Wqk  = sym(g_Wqk);   float* Wvo  = sym(g_Wvo);
    float* bq   = sym(g_bq);    float* bv   = sym(g_bv);
    float* rvec = sym(g_rvec);  float* bvo  = sym(g_bvo);  float* rv  = sym(g_rv);
    float* G    = sym(g_G);     float* FVo  = sym(g_FVo);  float* S   = sym(g_S);
    float* P1   = sym(g_P1);    float* P3   = sym(g_P3);
    float* Q1   = sym(g_Q1);    float* Q3   = sym(g_Q3);

    const float scale = 1.0f / sqrtf((float)ATT);

    cudaMemsetAsync(agg1, 0, sizeof(float) * NTOT * FIN, 0);
    cudaMemsetAsync(agg2, 0, sizeof(float) * NTOT * H1D, 0);

    // ---- GNN front-end ----
    k_edgew<<<EDIR / 256, 256>>>(ea, wembW, wembB);
    k_sc1<<<EDIR / 256, 256>>>(edges, x);
    k_gc1<<<NTOT * H1D / 256, 256>>>(x, gc1Wrel, gc1brel, gc1Wroot);
    k_sc2<<<EDIR, 64>>>(edges);
    gemm<false, false, false, false>(agg2, gc2Wrel, h2, nullptr,
                                     NTOT, H2D, H1D, H1D, H2D, H2D, 0, 0, 0, 0, 1.f, 1);
    gemm<false, true, true, true>(h1, gc2Wroot, h2, gc2brel,
                                  NTOT, H2D, H1D, H1D, H2D, H2D, 0, 0, 0, 0, 1.f, 1);
    k_gnorm<<<BGR, H2D>>>(gnw, gnb, gnms);

    // ---- edge selection + sort + feature assembly ----
    k_sort<<<BGR, 256>>>(edges);
    k_feat<<<EKEEP, 256>>>(ea, eW, ebias);

    // ---- weight folding ----
    gemm<false, false, false, false>(qkvW + 0,    inWq, Wq, nullptr, ATT, ATT, ATT, 3 * ATT, ATT, ATT, 0, 0, 0, 0, 1.f, 1);
    gemm<false, false, false, false>(qkvW + ATT,  inWk, Wk, nullptr, ATT, ATT, ATT, 3 * ATT, ATT, ATT, 0, 0, 0, 0, 1.f, 1);
    gemm<false, false, false, false>(qkvW + 2*ATT,inWv, Wv, nullptr, ATT, ATT, ATT, 3 * ATT, ATT, ATT, 0, 0, 0, 0, 1.f, 1);
    k_vecmat<<<ATT / 256, 256>>>(qkvb + 0,     inWq, inbq, bq, ATT, ATT, ATT);
    k_vecmat<<<ATT / 256, 256>>>(qkvb + 2*ATT, inWv, inbv, bv, ATT, ATT, ATT);
    k_matvecr<<<ATT, 256>>>(Wk, bq, rvec, scale);           // r = scale * Wk_eff @ bq_eff
    k_vecmat<<<ATT / 256, 256>>>(bv, outW, outb, bvo, ATT, ATT, ATT);
    gemm<true,  false, false, false>(Wq, Wk, Wqk, nullptr, ATT, ATT, ATT, ATT, ATT, ATT, 0, 0, 0, 0, scale, 1);
    gemm<false, false, false, false>(Wv, outW, Wvo, nullptr, ATT, ATT, ATT, ATT, ATT, ATT, 0, 0, 0, 0, 1.f, 1);

    // ---- decomposed projections: G = P1[src] + emb@Wqk_mid + P3[dst] ----
    gemm<false, false, false, false>(feat + 512, Wqk + (long long)512 * ATT, G, nullptr,
                                     EKEEP, ATT, 512, ATT, ATT, ATT, 0, 0, 0, 0, 1.f, 1);
    gemm<false, false, false, true>(feat + 512, Wvo + (long long)512 * ATT, FVo, bvo,
                                    EKEEP, ATT, 512, ATT, ATT, ATT, 0, 0, 0, 0, 1.f, 1);
    gemm<false, false, false, false>(h2, Wqk, P1, nullptr,
                                     NTOT, ATT, 512, H2D, ATT, ATT, 0, 0, 0, 0, 1.f, 1);
    gemm<false, false, false, false>(h2, Wqk + (long long)1024 * ATT, P3, nullptr,
                                     NTOT, ATT, 512, H2D, ATT, ATT, 0, 0, 0, 0, 1.f, 1);
    gemm<false, false, false, false>(h2, Wvo, Q1, nullptr,
                                     NTOT, ATT, 512, H2D, ATT, ATT, 0, 0, 0, 0, 1.f, 1);
    gemm<false, false, false, false>(h2, Wvo + (long long)1024 * ATT, Q3, nullptr,
                                     NTOT, ATT, 512, H2D, ATT, ATT, 0, 0, 0, 0, 1.f, 1);
    k_gadd<<<EKEEP, 256>>>();

    // ---- attention ----
    k_rowdot<<<EKEEP, 256>>>();                             // rv = feat @ r
    // scores[b] = G[b] @ feat[b]^T + rv[b]  (per-column bias)
    gemm<true, false, false, true>(G, feat, S, rv,
                                   EU, EU, ATT, ATT, ATT, EU,
                                   (long long)EU * ATT, (long long)EU * ATT,
                                   (long long)EU * EU, EU, 1.f, BGR);
    k_softmax<<<EKEEP, 256>>>();
    // feat += S[b] @ FVo[b]
    gemm<false, true, false, false>(S, FVo, feat, nullptr,
                                    EU, ATT, EU, EU, ATT, ATT,
                                    (long long)EU * EU, (long long)EU * ATT,
                                    (long long)EU * ATT, 0, 1.f, BGR);

    // ---- LN + head + pairing ----
    k_ln_head<<<EKEEP, 256>>>(lng, lnb, hW, hb);
    k_final<<<(BGR * 128) / 256, 256>>>(ea, (float*)d_out);
}